// round 11
// baseline (speedup 1.0000x reference)
#include <cuda_runtime.h>
#include <cstdint>

#define B   8
#define C   512
#define K   19
#define HW  16384
#define INV_HW (1.0f / 16384.0f)

typedef unsigned long long u64;

// scratch (__device__ globals: allocation-free rule)
__device__ float g_cf[B * K * C];      // class_feat accumulator
__device__ float g_filt[B * K * C];    // dynamic filters
__device__ float g_mask[B * K * HW];   // sigmoid mask (~10 MB)

// ---- packed f32x2 helpers ----
__device__ __forceinline__ u64 pack2(float lo, float hi) {
    u64 r; asm("mov.b64 %0, {%1, %2};" : "=l"(r) : "f"(lo), "f"(hi)); return r;
}
__device__ __forceinline__ void fma2(u64& d, u64 a, u64 b) {
    asm("fma.rn.f32x2 %0, %1, %2, %0;" : "+l"(d) : "l"(a), "l"(b));
}
__device__ __forceinline__ float2 unpack2(u64 v) {
    float2 f; asm("mov.b64 {%0, %1}, %2;" : "=f"(f.x), "=f"(f.y) : "l"(v)); return f;
}
__device__ __forceinline__ float sigmoidf_(float z) {
    return 1.0f / (1.0f + __expf(-z));
}

#define KG 10   // k's per group (group0: k 0..9, group1: k 10..18 + zero pad)

// ---------------------------------------------------------------------------
// Kernel 0: zero class_feat accumulator
// ---------------------------------------------------------------------------
__global__ void zero_cf_kernel() {
    int i = blockIdx.x * blockDim.x + threadIdx.x;
    if (i < B * K * C) g_cf[i] = 0.0f;
}

// ---------------------------------------------------------------------------
// Kernel 1: mask = sigmoid(Wm @ x + bm) -> g_mask   (FFMA2, k-split)
//   grid = (HW/256, 2 kgroups, B) = 1024 blocks, block = 128
//   thread = 2 adjacent px x 10 k; acc lanes = c-pairs (20 u64 accs)
//   per 4c: 4 LDG.64 + 4 packs + 10 LDS.128 (natural w-pairs) + 40 FFMA2
// ---------------------------------------------------------------------------
#define MK_TPB 128
#define MK_T   256

__global__ __launch_bounds__(MK_TPB, 6) void mask_kernel(
    const float* __restrict__ x,
    const float* __restrict__ Wm,
    const float* __restrict__ bm)
{
    __shared__ __align__(16) float sW[KG * C];   // 20480 B (this kgroup only)

    const int tid = threadIdx.x;
    const int kg  = blockIdx.y;
    const int b   = blockIdx.z;
    const int p0  = blockIdx.x * MK_T;
    const int kbase = kg * KG;

    for (int i = tid; i < KG * C / 4; i += MK_TPB) {
        int k = i / (C / 4);
        int kk = kbase + k;
        float4 v = (kk < K) ? ((const float4*)Wm)[kk * (C / 4) + (i - k * (C / 4))]
                            : make_float4(0.f, 0.f, 0.f, 0.f);
        ((float4*)sW)[i] = v;
    }
    __syncthreads();

    const int px = p0 + 2 * tid;
    const float* __restrict__ xc = x + (size_t)b * C * HW + px;

    u64 accA[KG], accB[KG];   // lanes = (even-c, odd-c) partial sums
#pragma unroll
    for (int k = 0; k < KG; k++) { accA[k] = 0ULL; accB[k] = 0ULL; }

#pragma unroll 2
    for (int c = 0; c < C; c += 4) {
        float2 l0 = *(const float2*)(xc);            // ch c  : (pxA,pxB)
        float2 l1 = *(const float2*)(xc + HW);
        float2 l2 = *(const float2*)(xc + 2 * HW);
        float2 l3 = *(const float2*)(xc + 3 * HW);
        xc += 4 * HW;
        u64 xA01 = pack2(l0.x, l1.x);   // pxA, (c,c+1)
        u64 xB01 = pack2(l0.y, l1.y);
        u64 xA23 = pack2(l2.x, l3.x);   // pxA, (c+2,c+3)
        u64 xB23 = pack2(l2.y, l3.y);
#pragma unroll
        for (int k = 0; k < KG; k++) {
            ulonglong2 w = *(const ulonglong2*)&sW[k * C + c];  // LDS.128 bcast
            fma2(accA[k], w.x, xA01);
            fma2(accB[k], w.x, xB01);
            fma2(accA[k], w.y, xA23);
            fma2(accB[k], w.y, xB23);
        }
    }

#pragma unroll
    for (int k = 0; k < KG; k++) {
        int kk = kbase + k;
        if (kk < K) {
            float bv = __ldg(&bm[kk]);
            float2 a = unpack2(accA[k]);
            float2 c2 = unpack2(accB[k]);
            float2 m;
            m.x = sigmoidf_(a.x + a.y + bv);
            m.y = sigmoidf_(c2.x + c2.y + bv);
            *(float2*)&g_mask[((size_t)b * K + kk) * HW + px] = m;
        }
    }
}

// ---------------------------------------------------------------------------
// Kernel 2: pooling  g_cf[b,k,c] += sum_p mask[b,k,p]*x[b,c,p]  (FFMA2, k-split)
//   grid = (HW/256, 4, B) = 2048 blocks (y: bit0=kgroup, bit1=chgroup)
//   block = 128; thread = 2 channels x 10 k; acc lanes = p-pairs (20 u64)
//   per 4p: 2 LDG.128 + 10 LDS.128 + 40 FFMA2  (zero pack movs)
// ---------------------------------------------------------------------------
#define PL_TPB 128
#define PL_T   256

__global__ __launch_bounds__(PL_TPB, 6) void pool_kernel(const float* __restrict__ x)
{
    __shared__ __align__(16) float sM[KG * PL_T];   // 10240 B

    const int tid = threadIdx.x;
    const int kg  = blockIdx.y & 1;
    const int chg = blockIdx.y >> 1;
    const int b   = blockIdx.z;
    const int p0  = blockIdx.x * PL_T;
    const int kbase = kg * KG;

    {
        const float* mb = g_mask + (size_t)b * K * HW + p0;
        for (int i = tid; i < KG * (PL_T / 4); i += PL_TPB) {
            int k = i / (PL_T / 4);
            int kk = kbase + k;
            int j = i - k * (PL_T / 4);
            float4 v = (kk < K) ? *(const float4*)(mb + (size_t)kk * HW + j * 4)
                                : make_float4(0.f, 0.f, 0.f, 0.f);
            ((float4*)sM)[i] = v;
        }
    }
    __syncthreads();

    const int ch0 = chg * 256 + tid;
    const int ch1 = ch0 + 128;
    const float* __restrict__ xp0 = x + (size_t)b * C * HW + (size_t)ch0 * HW + p0;
    const float* __restrict__ xp1 = x + (size_t)b * C * HW + (size_t)ch1 * HW + p0;

    u64 a0[KG], a1[KG];
#pragma unroll
    for (int k = 0; k < KG; k++) { a0[k] = 0ULL; a1[k] = 0ULL; }

#pragma unroll 2
    for (int p = 0; p < PL_T; p += 4) {
        ulonglong2 v0 = *(const ulonglong2*)(xp0 + p);  // natural p-pairs
        ulonglong2 v1 = *(const ulonglong2*)(xp1 + p);
#pragma unroll
        for (int k = 0; k < KG; k++) {
            ulonglong2 m = *(const ulonglong2*)&sM[k * PL_T + p];  // LDS.128 bcast
            fma2(a0[k], m.x, v0.x); fma2(a0[k], m.y, v0.y);
            fma2(a1[k], m.x, v1.x); fma2(a1[k], m.y, v1.y);
        }
    }

#pragma unroll
    for (int k = 0; k < KG; k++) {
        int kk = kbase + k;
        if (kk < K) {
            float2 s = unpack2(a0[k]);
            atomicAdd(&g_cf[((size_t)b * K + kk) * C + ch0], s.x + s.y);
            float2 t = unpack2(a1[k]);
            atomicAdd(&g_cf[((size_t)b * K + kk) * C + ch1], t.x + t.y);
        }
    }
}

// ---------------------------------------------------------------------------
// Kernel 3: filters (R8-proven, 21 us) — warp-per-output, Wf read once
// ---------------------------------------------------------------------------
__global__ __launch_bounds__(256) void filters_kernel(
    const float* __restrict__ Wf,
    const float* __restrict__ bf)
{
    __shared__ __align__(16) float scf[B * C];   // 16 KB

    const int k    = blockIdx.x;
    const int tid  = threadIdx.x;
    const int warp = tid >> 5;
    const int lane = tid & 31;

    for (int i = tid; i < B * C; i += 256) {
        int bb = i >> 9, cc = i & 511;
        scf[i] = g_cf[((size_t)bb * K + k) * C + cc] * INV_HW;
    }
    __syncthreads();

    const int o = blockIdx.y * 8 + warp;
    const float4* __restrict__ wrow4 = (const float4*)(Wf + ((size_t)k * C + o) * C);
    const float4* __restrict__ scf4  = (const float4*)scf;

    float acc[B];
#pragma unroll
    for (int bb = 0; bb < B; bb++) acc[bb] = 0.0f;

#pragma unroll
    for (int i = 0; i < 4; i++) {
        float4 w = wrow4[i * 32 + lane];
#pragma unroll
        for (int bb = 0; bb < B; bb++) {
            float4 f = scf4[bb * 128 + i * 32 + lane];
            acc[bb] += w.x * f.x + w.y * f.y + w.z * f.z + w.w * f.w;
        }
    }

#pragma unroll
    for (int bb = 0; bb < B; bb++) {
#pragma unroll
        for (int s = 16; s > 0; s >>= 1)
            acc[bb] += __shfl_xor_sync(0xffffffffu, acc[bb], s);
    }

    if (lane == 0) {
        float bias = __ldg(&bf[k * C + o]);
#pragma unroll
        for (int bb = 0; bb < B; bb++)
            g_filt[((size_t)bb * K + k) * C + o] = acc[bb] + bias;
    }
}

// ---------------------------------------------------------------------------
// Kernel 4: pred[b,k,p] = sum_c filters[b,k,c]*x[b,c,p]  (FFMA2, k-split)
//   identical structure to mask_kernel (no sigmoid), writes d_out
// ---------------------------------------------------------------------------
__global__ __launch_bounds__(MK_TPB, 6) void pred_kernel(
    const float* __restrict__ x,
    float* __restrict__ out)
{
    __shared__ __align__(16) float sF[KG * C];   // 20480 B

    const int tid = threadIdx.x;
    const int kg  = blockIdx.y;
    const int b   = blockIdx.z;
    const int p0  = blockIdx.x * MK_T;
    const int kbase = kg * KG;

    {
        const float4* fb = (const float4*)(g_filt + (size_t)b * K * C);
        for (int i = tid; i < KG * C / 4; i += MK_TPB) {
            int k = i / (C / 4);
            int kk = kbase + k;
            float4 v = (kk < K) ? fb[kk * (C / 4) + (i - k * (C / 4))]
                                : make_float4(0.f, 0.f, 0.f, 0.f);
            ((float4*)sF)[i] = v;
        }
    }
    __syncthreads();

    const int px = p0 + 2 * tid;
    const float* __restrict__ xc = x + (size_t)b * C * HW + px;

    u64 accA[KG], accB[KG];
#pragma unroll
    for (int k = 0; k < KG; k++) { accA[k] = 0ULL; accB[k] = 0ULL; }

#pragma unroll 2
    for (int c = 0; c < C; c += 4) {
        float2 l0 = *(const float2*)(xc);
        float2 l1 = *(const float2*)(xc + HW);
        float2 l2 = *(const float2*)(xc + 2 * HW);
        float2 l3 = *(const float2*)(xc + 3 * HW);
        xc += 4 * HW;
        u64 xA01 = pack2(l0.x, l1.x);
        u64 xB01 = pack2(l0.y, l1.y);
        u64 xA23 = pack2(l2.x, l3.x);
        u64 xB23 = pack2(l2.y, l3.y);
#pragma unroll
        for (int k = 0; k < KG; k++) {
            ulonglong2 w = *(const ulonglong2*)&sF[k * C + c];
            fma2(accA[k], w.x, xA01);
            fma2(accB[k], w.x, xB01);
            fma2(accA[k], w.y, xA23);
            fma2(accB[k], w.y, xB23);
        }
    }

#pragma unroll
    for (int k = 0; k < KG; k++) {
        int kk = kbase + k;
        if (kk < K) {
            float2 a = unpack2(accA[k]);
            float2 c2 = unpack2(accB[k]);
            float2 o = make_float2(a.x + a.y, c2.x + c2.y);
            *(float2*)&out[((size_t)b * K + kk) * HW + px] = o;
        }
    }
}

// ---------------------------------------------------------------------------
extern "C" void kernel_launch(void* const* d_in, const int* in_sizes, int n_in,
                              void* d_out, int out_size)
{
    const float* x  = (const float*)d_in[0];
    const float* Wm = (const float*)d_in[1];
    const float* bm = (const float*)d_in[2];
    const float* Wf = (const float*)d_in[3];
    const float* bf = (const float*)d_in[4];
    float* out = (float*)d_out;

    zero_cf_kernel<<<(B * K * C + 255) / 256, 256>>>();
    mask_kernel<<<dim3(HW / MK_T, 2, B), MK_TPB>>>(x, Wm, bm);
    pool_kernel<<<dim3(HW / PL_T, 4, B), PL_TPB>>>(x);
    filters_kernel<<<dim3(K, C / 8), 256>>>(Wf, bf);
    pred_kernel<<<dim3(HW / MK_T, 2, B), MK_TPB>>>(x, out);
}